// round 1
// baseline (speedup 1.0000x reference)
#include <cuda_runtime.h>

#define N_NODES 100000
#define IN_DIM  64
#define HID     32

// Scratch: __device__ globals (no allocation allowed in kernel_launch)
__device__ float g_h[N_NODES * HID];     // (X W) * norm_src  [N, 32]  = 12.8 MB
__device__ float g_degout[N_NODES];
__device__ float g_degin[N_NODES];

// ---------------------------------------------------------------------------
// 0) zero the output accumulator (d_out is poisoned 0xAA) and degree arrays
// ---------------------------------------------------------------------------
__global__ void zero_kernel(float4* out4, int n4) {
    int stride = gridDim.x * blockDim.x;
    for (int i = blockIdx.x * blockDim.x + threadIdx.x; i < n4; i += stride)
        out4[i] = make_float4(0.f, 0.f, 0.f, 0.f);
    for (int i = blockIdx.x * blockDim.x + threadIdx.x; i < N_NODES; i += stride) {
        g_degout[i] = 0.f;
        g_degin[i]  = 0.f;
    }
}

// ---------------------------------------------------------------------------
// 1) degrees: out-degree of src, in-degree of dst
// ---------------------------------------------------------------------------
__global__ void deg_kernel(const int* __restrict__ src,
                           const int* __restrict__ dst, int e) {
    int i = blockIdx.x * blockDim.x + threadIdx.x;
    if (i < e) {
        atomicAdd(&g_degout[src[i]], 1.f);
        atomicAdd(&g_degin [dst[i]], 1.f);
    }
}

// ---------------------------------------------------------------------------
// 2) h = (X @ W) * norm_src.  One warp per row; W staged in smem.
// ---------------------------------------------------------------------------
__global__ void gemm_kernel(const float* __restrict__ X,
                            const float* __restrict__ W, int n) {
    __shared__ float Ws[IN_DIM * HID];
    for (int i = threadIdx.x; i < IN_DIM * HID; i += blockDim.x)
        Ws[i] = W[i];
    __syncthreads();

    int row = blockIdx.x * (blockDim.x / HID) + threadIdx.x / HID;
    int col = threadIdx.x % HID;
    if (row >= n) return;

    const float* x = X + row * IN_DIM;
    float acc = 0.f;
#pragma unroll
    for (int k = 0; k < IN_DIM; k++)
        acc += x[k] * Ws[k * HID + col];   // x[k]: warp-uniform broadcast load

    float nrm = rsqrtf(fmaxf(g_degout[row], 1.f));
    g_h[row * HID + col] = acc * nrm;
}

// ---------------------------------------------------------------------------
// 3) edge scatter: agg[dst] += h[src].  8 threads/edge, each owns a float4
//    chunk; vectorized no-return reduction (red.global.add.v4.f32) quarters
//    the L2 atomic op count vs scalar atomicAdd.
// ---------------------------------------------------------------------------
__global__ void scatter_kernel(const int* __restrict__ src,
                               const int* __restrict__ dst,
                               float* __restrict__ out, int e) {
    int i = blockIdx.x * blockDim.x + threadIdx.x;   // i in [0, e*8)
    if (i >= e * 8) return;
    int eid = i >> 3;
    int c   = (i & 7) << 2;                          // chunk 0..7 -> float offset
    int s = src[eid];
    int d = dst[eid];
    float4 v = *reinterpret_cast<const float4*>(g_h + s * HID + c);
    float* p = out + d * HID + c;
    asm volatile("red.global.add.v4.f32 [%0], {%1,%2,%3,%4};"
                 :: "l"(p), "f"(v.x), "f"(v.y), "f"(v.z), "f"(v.w)
                 : "memory");
}

// ---------------------------------------------------------------------------
// 4) out = relu(agg * norm_dst + b), in place
// ---------------------------------------------------------------------------
__global__ void fin_kernel(float* __restrict__ out,
                           const float* __restrict__ b, int n) {
    int i = blockIdx.x * blockDim.x + threadIdx.x;   // i in [0, n*HID)
    if (i >= n * HID) return;
    int row = i / HID;
    int col = i % HID;
    float nrm = rsqrtf(fmaxf(g_degin[row], 1.f));
    float v = out[i] * nrm + b[col];
    out[i] = fmaxf(v, 0.f);
}

// ---------------------------------------------------------------------------
extern "C" void kernel_launch(void* const* d_in, const int* in_sizes, int n_in,
                              void* d_out, int out_size) {
    const float* features = (const float*)d_in[0];   // [N, 64]
    const int*   src      = (const int*)  d_in[1];   // [E]
    const int*   dst      = (const int*)  d_in[2];   // [E]
    const float* W        = (const float*)d_in[3];   // [64, 32]
    const float* b        = (const float*)d_in[4];   // [32]
    float*       out      = (float*)d_out;           // [N, 32]

    int n = in_sizes[0] / IN_DIM;                    // 100000
    int e = in_sizes[1];                             // 1600000

    // 0) zero agg (=d_out) + degree arrays
    int n4 = (n * HID) / 4;
    zero_kernel<<<2048, 256>>>((float4*)out, n4);

    // 1) degrees
    deg_kernel<<<(e + 255) / 256, 256>>>(src, dst, e);

    // 2) h = (X W) * norm_src   (8 rows per 256-thread block)
    gemm_kernel<<<(n + 7) / 8, 256>>>(features, W, n);

    // 3) scatter-add over edges (8 threads per edge)
    int scatter_threads = e * 8;
    scatter_kernel<<<(scatter_threads + 255) / 256, 256>>>(src, dst, out, e);

    // 4) finalize
    fin_kernel<<<(n * HID + 255) / 256, 256>>>(out, b, n);
}

// round 2
// speedup vs baseline: 1.2251x; 1.2251x over previous
#include <cuda_runtime.h>

#define N_NODES 100000
#define IN_DIM  64
#define HID     32

// Scratch: __device__ globals (no allocation allowed in kernel_launch)
__device__ float g_h[N_NODES * HID];     // (X W) * norm_src  [N, 32]
__device__ float g_degout[N_NODES];
__device__ float g_degin[N_NODES];

// ---------------------------------------------------------------------------
// 0) zero the output accumulator (d_out is poisoned 0xAA) and degree arrays
// ---------------------------------------------------------------------------
__global__ void zero_kernel(float4* out4, int n4) {
    int stride = gridDim.x * blockDim.x;
    for (int i = blockIdx.x * blockDim.x + threadIdx.x; i < n4; i += stride)
        out4[i] = make_float4(0.f, 0.f, 0.f, 0.f);
    for (int i = blockIdx.x * blockDim.x + threadIdx.x; i < N_NODES; i += stride) {
        g_degout[i] = 0.f;
        g_degin[i]  = 0.f;
    }
}

// ---------------------------------------------------------------------------
// 1) degrees: int4-vectorized index loads, 4 edges per thread
// ---------------------------------------------------------------------------
__global__ void deg_kernel(const int4* __restrict__ src4,
                           const int4* __restrict__ dst4, int e4) {
    int i = blockIdx.x * blockDim.x + threadIdx.x;
    if (i >= e4) return;
    int4 s = src4[i];
    int4 d = dst4[i];
    atomicAdd(&g_degout[s.x], 1.f);
    atomicAdd(&g_degout[s.y], 1.f);
    atomicAdd(&g_degout[s.z], 1.f);
    atomicAdd(&g_degout[s.w], 1.f);
    atomicAdd(&g_degin[d.x], 1.f);
    atomicAdd(&g_degin[d.y], 1.f);
    atomicAdd(&g_degin[d.z], 1.f);
    atomicAdd(&g_degin[d.w], 1.f);
}
// tail edges (e % 4)
__global__ void deg_tail_kernel(const int* __restrict__ src,
                                const int* __restrict__ dst,
                                int start, int e) {
    int i = start + blockIdx.x * blockDim.x + threadIdx.x;
    if (i < e) {
        atomicAdd(&g_degout[src[i]], 1.f);
        atomicAdd(&g_degin [dst[i]], 1.f);
    }
}

// ---------------------------------------------------------------------------
// 2) h = (X @ W) * norm_src.  8 rows/block; X tile staged in smem via float4,
//    W staged in smem.  Per-thread inner loop reads smem only (conflict-free).
// ---------------------------------------------------------------------------
__global__ void gemm_kernel(const float4* __restrict__ X4,
                            const float* __restrict__ W, int n) {
    __shared__ float Ws[IN_DIM * HID];     // 8 KB
    __shared__ float4 xs4[8 * IN_DIM / 4]; // 8 rows * 64 floats = 2 KB

    // stage W (2048 floats, 8 per thread)
    for (int i = threadIdx.x; i < IN_DIM * HID; i += blockDim.x)
        Ws[i] = W[i];

    int row0 = blockIdx.x * 8;
    // stage 8 rows of X: 512 floats = 128 float4, coalesced
    if (threadIdx.x < 128) {
        int idx = row0 * (IN_DIM / 4) + threadIdx.x;
        if (row0 + (threadIdx.x >> 4) < n)     // row = row0 + t/16
            xs4[threadIdx.x] = X4[idx];
    }
    __syncthreads();

    int row = row0 + (threadIdx.x >> 5);       // tid/32
    int col = threadIdx.x & 31;
    if (row >= n) return;

    const float4* xr = xs4 + (threadIdx.x >> 5) * (IN_DIM / 4);
    float acc = 0.f;
#pragma unroll
    for (int k4 = 0; k4 < IN_DIM / 4; k4++) {
        float4 x = xr[k4];                     // broadcast within 32-thread group
        int k = k4 * 4;
        acc += x.x * Ws[(k + 0) * HID + col];
        acc += x.y * Ws[(k + 1) * HID + col];
        acc += x.z * Ws[(k + 2) * HID + col];
        acc += x.w * Ws[(k + 3) * HID + col];
    }

    float nrm = rsqrtf(fmaxf(g_degout[row], 1.f));
    g_h[row * HID + col] = acc * nrm;
}

// ---------------------------------------------------------------------------
// 3) edge scatter: agg[dst] += h[src].  512-edge tiles; indices staged in
//    smem (coalesced, 2 global idx loads per edge instead of 16), then
//    8 threads/edge issue float4 gather + red.global.add.v4.f32.
// ---------------------------------------------------------------------------
#define TILE 512
__global__ void scatter_kernel(const int* __restrict__ src,
                               const int* __restrict__ dst,
                               float* __restrict__ out, int e) {
    __shared__ int s_src[TILE];
    __shared__ int s_dst[TILE];

    int base = blockIdx.x * TILE;
    int tile_n = min(TILE, e - base);

    // stage indices: 2 per thread, coalesced
    for (int i = threadIdx.x; i < tile_n; i += blockDim.x) {
        s_src[i] = src[base + i];
        s_dst[i] = dst[base + i];
    }
    __syncthreads();

    int sub = threadIdx.x >> 3;          // 0..31  (edge slot within pass)
    int c   = (threadIdx.x & 7) << 2;    // float offset 0,4,...,28

#pragma unroll 4
    for (int k = 0; k < TILE; k += 32) {
        int el = k + sub;
        if (el >= tile_n) break;
        int s = s_src[el];               // broadcast LDS
        int d = s_dst[el];
        float4 v = *reinterpret_cast<const float4*>(g_h + s * HID + c);
        float* p = out + d * HID + c;
        asm volatile("red.global.add.v4.f32 [%0], {%1,%2,%3,%4};"
                     :: "l"(p), "f"(v.x), "f"(v.y), "f"(v.z), "f"(v.w)
                     : "memory");
    }
}

// ---------------------------------------------------------------------------
// 4) out = relu(agg * norm_dst + b), in place, float4-vectorized
// ---------------------------------------------------------------------------
__global__ void fin_kernel(float4* __restrict__ out4,
                           const float* __restrict__ b, int n) {
    int i = blockIdx.x * blockDim.x + threadIdx.x;   // i in [0, n*8)
    if (i >= n * (HID / 4)) return;
    int row  = i >> 3;                // /8 float4 per row
    int col4 = (i & 7) << 2;
    float nrm = rsqrtf(fmaxf(g_degin[row], 1.f));
    float4 v = out4[i];
    v.x = fmaxf(v.x * nrm + b[col4 + 0], 0.f);
    v.y = fmaxf(v.y * nrm + b[col4 + 1], 0.f);
    v.z = fmaxf(v.z * nrm + b[col4 + 2], 0.f);
    v.w = fmaxf(v.w * nrm + b[col4 + 3], 0.f);
    out4[i] = v;
}

// ---------------------------------------------------------------------------
extern "C" void kernel_launch(void* const* d_in, const int* in_sizes, int n_in,
                              void* d_out, int out_size) {
    const float* features = (const float*)d_in[0];   // [N, 64]
    const int*   src      = (const int*)  d_in[1];   // [E]
    const int*   dst      = (const int*)  d_in[2];   // [E]
    const float* W        = (const float*)d_in[3];   // [64, 32]
    const float* b        = (const float*)d_in[4];   // [32]
    float*       out      = (float*)d_out;           // [N, 32]

    int n = in_sizes[0] / IN_DIM;                    // 100000
    int e = in_sizes[1];                             // 1600000

    // 0) zero agg (=d_out) + degree arrays
    int n4 = (n * HID) / 4;
    zero_kernel<<<2048, 256>>>((float4*)out, n4);

    // 1) degrees (vectorized, 4 edges/thread + tail)
    int e4 = e / 4;
    if (e4 > 0)
        deg_kernel<<<(e4 + 255) / 256, 256>>>((const int4*)src, (const int4*)dst, e4);
    if (e4 * 4 < e)
        deg_tail_kernel<<<1, 256>>>(src, dst, e4 * 4, e);

    // 2) h = (X W) * norm_src   (8 rows per 256-thread block, smem-tiled)
    gemm_kernel<<<(n + 7) / 8, 256>>>((const float4*)features, W, n);

    // 3) scatter-add over edges (512-edge tiles, smem-staged indices)
    scatter_kernel<<<(e + TILE - 1) / TILE, 256>>>(src, dst, out, e);

    // 4) finalize (float4)
    fin_kernel<<<(n * (HID / 4) + 255) / 256, 256>>>((float4*)out, b, n);
}